// round 14
// baseline (speedup 1.0000x reference)
#include <cuda_runtime.h>

#define XD 38
#define YD 24
#define ZD 24
#define RV (XD*YD*ZD)          // 21888
#define BB 16
#define CC 64
#define NN 16384
#define TOTVOX (BB*RV)         // 350208 (= 5472*64)
#define NPTS   (BB*NN)         // 262144
#define FIN_BLOCKS (TOTVOX/64)      // 5472
#define GROUPS_PER_BATCH (RV/64)    // 342

// scratch (__device__ globals; zero-initialized at load; self-cleaned every launch)
__device__ __align__(16) int   g_cnt[TOTVOX];                  // per-voxel count
__device__ __align__(16) float g_stage[(size_t)TOTVOX * CC];   // [B, R, C] accumulator (~90MB)
__device__ __align__(16) float g_zero[CC];                     // never written: stays zero

__device__ __forceinline__ void red_add_v4(float* addr, float a, float b, float c, float d) {
    asm volatile("red.global.add.v4.f32 [%0], {%1, %2, %3, %4};"
                 :: "l"(addr), "f"(a), "f"(b), "f"(c), "f"(d) : "memory");
}

__device__ __forceinline__ int coord_to_flat(float cx, float cy, float cz) {
    int ix = (int)floorf(cx / 0.3f) + 19;
    int iy = (int)floorf(cy / 0.3f) + 12;
    int iz = (int)floorf(cz / 0.2f) + 12;
    bool valid = (ix >= 0) & (ix < XD) & (iy >= 0) & (iy < YD) & (iz >= 0) & (iz < ZD);
    return valid ? (ix * (YD*ZD) + iy * ZD + iz) : -1;
}

// ---------------- index: per-voxel counts, 4 pts/thread vectorized ----------------
__global__ __launch_bounds__(256)
void index_k(const float4* __restrict__ coords4) {
    int t = blockIdx.x * blockDim.x + threadIdx.x;
    int p0 = t * 4;
    if (p0 >= NPTS) return;
    float4 a = coords4[t*3 + 0];
    float4 b = coords4[t*3 + 1];
    float4 c = coords4[t*3 + 2];
    float px[4] = {a.x, a.w, b.z, c.y};
    float py[4] = {a.y, b.x, b.w, c.z};
    float pz[4] = {a.z, b.y, c.x, c.w};
    int bidx = p0 >> 14;                         // batch (4 pts never cross batch)
    #pragma unroll
    for (int k = 0; k < 4; k++) {
        int flat = coord_to_flat(px[k], py[k], pz[k]);
        if (flat >= 0) atomicAdd(&g_cnt[bidx*RV + flat], 1);
    }
}

// ---------------- scatter (PDL secondary): feature phase overlaps index_k ------------
__global__ __launch_bounds__(256)
void scatter_k(const float* __restrict__ feat, const float* __restrict__ coords) {
    __shared__ float sm[64][33];
    __shared__ int   s_flat[32];      // phase A: flat; phase B: flat|SINGLE_BIT tag
    int b  = blockIdx.y;
    int p0 = blockIdx.x * 32;
    int t  = threadIdx.x;

    // ---- phase A: independent of g_cnt (overlaps index_k under PDL) ----
    if (t < 32) {
        const float* cp = coords + ((size_t)b * NN + p0 + t) * 3;
        s_flat[t] = coord_to_flat(cp[0], cp[1], cp[2]);
    }
    int j  = t & 31;
    int rb = t >> 5;
    const float* fb = feat + (size_t)b * CC * NN + p0 + j;
    #pragma unroll
    for (int k = 0; k < 8; k++) {
        int row = rb + k * 8;
        sm[row][j] = __ldcs(&fb[(size_t)row * NN]);   // streamed once; keep L2 for staging
    }

    // ---- wait for index_k's counts to be final ----
    cudaGridDependencySynchronize();

    if (t < 32) {
        int flat = s_flat[t];
        if (flat >= 0 && g_cnt[b*RV + flat] == 1)
            s_flat[t] = flat | 0x40000000;            // singleton marker
    }
    __syncthreads();

    int jp = t >> 3;                  // point in tile 0..31
    int q  = t & 7;                   // channel octet 0..7
    int tag = s_flat[jp];
    if (tag >= 0) {
        bool single = (tag & 0x40000000) != 0;
        int flat = tag & 0x3FFFFFFF;
        float* dst = g_stage + ((size_t)(b * RV + flat) * CC) + q * 8;
        int c0 = q * 8;
        float4 x = make_float4(sm[c0+0][jp], sm[c0+1][jp], sm[c0+2][jp], sm[c0+3][jp]);
        float4 y = make_float4(sm[c0+4][jp], sm[c0+5][jp], sm[c0+6][jp], sm[c0+7][jp]);
        if (single) {                 // sole writer of this row: plain stores (L2-resident)
            *reinterpret_cast<float4*>(dst)     = x;
            *reinterpret_cast<float4*>(dst + 4) = y;
        } else {                      // shared row: atomic reduction
            red_add_v4(dst,     x.x, x.y, x.z, x.w);
            red_add_v4(dst + 4, y.x, y.y, y.z, y.w);
        }
    }
}

// ---------------- finalize (PDL secondary): zero-row address steering ----------------
__global__ __launch_bounds__(256)
void finalize_k(float* __restrict__ out) {
    __shared__ float sm[64 * 65];     // [channel][voxel]
    __shared__ float s_inv[64];
    __shared__ int   s_cnt[64];
    int t = threadIdx.x;
    int gvbase = blockIdx.x * 64;

    cudaGridDependencySynchronize();  // everything below depends on scatter

    if (t < 64) {
        int c = g_cnt[gvbase + t];    // read, THEN clean (same thread -> ordered)
        s_cnt[t] = c;
        s_inv[t] = 1.f / (float)max(c, 1);
        g_cnt[gvbase + t] = 0;        // self-clean counts
    }
    __syncthreads();

    float4* stg4 = reinterpret_cast<float4*>(g_stage + (size_t)gvbase * CC);  // 1024 float4
    const float4* zero4 = reinterpret_cast<const float4*>(g_zero);

    // Address steering: loads stay UNCONDITIONAL (front-batched, MLP=4); empty
    // voxels read a 256B always-zero dummy row (L1/L2-hot) instead of DRAM.
    const float4* src[4];
    int cnts[4];
    #pragma unroll
    for (int k = 0; k < 4; k++) {
        int i   = t + 256 * k;
        int vox = i >> 4;
        int c4  = i & 15;
        cnts[k] = s_cnt[vox];
        src[k]  = (cnts[k] > 0) ? (const float4*)&stg4[i] : &zero4[c4];
    }
    float4 v[4];
    #pragma unroll
    for (int k = 0; k < 4; k++) v[k] = __ldcs(src[k]);
    #pragma unroll
    for (int k = 0; k < 4; k++) {
        int i   = t + 256 * k;
        int vox = i >> 4;
        int c4  = i & 15;
        float inv = s_inv[vox];
        int c0 = c4 * 4;
        sm[(c0+0) * 65 + vox] = v[k].x * inv;
        sm[(c0+1) * 65 + vox] = v[k].y * inv;
        sm[(c0+2) * 65 + vox] = v[k].z * inv;
        sm[(c0+3) * 65 + vox] = v[k].w * inv;
        if (cnts[k] > 1) stg4[i] = make_float4(0.f, 0.f, 0.f, 0.f);  // clean RED rows
    }
    __syncthreads();

    int b  = blockIdx.x / GROUPS_PER_BATCH;
    int vb = (blockIdx.x % GROUPS_PER_BATCH) * 64;
    int c  = t >> 2;                  // 0..63
    int q  = t & 3;                   // 0..3 -> 16 voxels each
    float* ob = out + ((size_t)(b * CC + c)) * RV + vb + q * 16;
    const float* sp = &sm[c * 65 + q * 16];
    #pragma unroll
    for (int k = 0; k < 4; k++) {
        __stcs(reinterpret_cast<float4*>(ob + k*4),
               make_float4(sp[k*4+0], sp[k*4+1], sp[k*4+2], sp[k*4+3]));  // never re-read
    }
}

extern "C" void kernel_launch(void* const* d_in, const int* in_sizes, int n_in,
                              void* d_out, int out_size) {
    const float* feat   = (const float*)d_in[0];   // [B, C, N]
    const float* coords = (const float*)d_in[1];   // [B, N, 3]
    float* out = (float*)d_out;                    // [B, C, X, Y, Z]

    index_k<<<NPTS / 4 / 256, 256>>>(reinterpret_cast<const float4*>(coords)); // 256 blocks

    cudaLaunchAttribute pdl[1];
    pdl[0].id = cudaLaunchAttributeProgrammaticStreamSerialization;
    pdl[0].val.programmaticStreamSerializationAllowed = 1;

    {   // scatter: PDL secondary of index
        cudaLaunchConfig_t cfg = {};
        cfg.gridDim  = dim3(NN / 32, BB);
        cfg.blockDim = dim3(256);
        cfg.stream   = 0;
        cfg.attrs    = pdl;
        cfg.numAttrs = 1;
        cudaLaunchKernelEx(&cfg, scatter_k, feat, coords);
    }
    {   // finalize: PDL secondary of scatter
        cudaLaunchConfig_t cfg = {};
        cfg.gridDim  = dim3(FIN_BLOCKS);
        cfg.blockDim = dim3(256);
        cfg.stream   = 0;
        cfg.attrs    = pdl;
        cfg.numAttrs = 1;
        cudaLaunchKernelEx(&cfg, finalize_k, out);
    }
}

// round 15
// speedup vs baseline: 1.0369x; 1.0369x over previous
#include <cuda_runtime.h>

#define XD 38
#define YD 24
#define ZD 24
#define RV (XD*YD*ZD)          // 21888
#define BB 16
#define CC 64
#define NN 16384
#define TOTVOX (BB*RV)         // 350208 (= 5472*64)
#define NPTS   (BB*NN)         // 262144
#define FIN_BLOCKS (TOTVOX/64)      // 5472
#define GROUPS_PER_BATCH (RV/64)    // 342

// scratch (__device__ globals; zero-initialized at load; self-cleaned every launch)
__device__ __align__(16) int   g_cnt[TOTVOX];                  // per-voxel count
__device__ __align__(16) float g_stage[(size_t)TOTVOX * CC];   // [B, R, C] accumulator (~90MB)

__device__ __forceinline__ void red_add_v4(float* addr, float a, float b, float c, float d) {
    asm volatile("red.global.add.v4.f32 [%0], {%1, %2, %3, %4};"
                 :: "l"(addr), "f"(a), "f"(b), "f"(c), "f"(d) : "memory");
}

__device__ __forceinline__ int coord_to_flat(float cx, float cy, float cz) {
    int ix = (int)floorf(cx / 0.3f) + 19;
    int iy = (int)floorf(cy / 0.3f) + 12;
    int iz = (int)floorf(cz / 0.2f) + 12;
    bool valid = (ix >= 0) & (ix < XD) & (iy >= 0) & (iy < YD) & (iz >= 0) & (iz < ZD);
    return valid ? (ix * (YD*ZD) + iy * ZD + iz) : -1;
}

// ---------------- index: per-voxel counts, 4 pts/thread vectorized ----------------
__global__ __launch_bounds__(256)
void index_k(const float4* __restrict__ coords4) {
    int t = blockIdx.x * blockDim.x + threadIdx.x;
    int p0 = t * 4;
    if (p0 >= NPTS) return;
    float4 a = coords4[t*3 + 0];
    float4 b = coords4[t*3 + 1];
    float4 c = coords4[t*3 + 2];
    float px[4] = {a.x, a.w, b.z, c.y};
    float py[4] = {a.y, b.x, b.w, c.z};
    float pz[4] = {a.z, b.y, c.x, c.w};
    int bidx = p0 >> 14;                         // batch (4 pts never cross batch)
    #pragma unroll
    for (int k = 0; k < 4; k++) {
        int flat = coord_to_flat(px[k], py[k], pz[k]);
        if (flat >= 0) atomicAdd(&g_cnt[bidx*RV + flat], 1);
    }
}

// ---------------- scatter (PDL secondary): feature phase overlaps index_k ------------
__global__ __launch_bounds__(256)
void scatter_k(const float* __restrict__ feat, const float* __restrict__ coords) {
    __shared__ float sm[64][33];
    __shared__ float s_crd[96];       // 32 points x 3 coords
    __shared__ int   s_flat[32];      // flat id, later flat|SINGLE_BIT tag
    int b  = blockIdx.y;
    int p0 = blockIdx.x * 32;
    int t  = threadIdx.x;

    // ---- phase A: independent of g_cnt (overlaps index_k under PDL) ----
    if (t < 24) {                     // 24 x float4 = 96 floats = 32 pts x 3
        const float4* cp4 = reinterpret_cast<const float4*>(coords + ((size_t)b * NN + p0) * 3);
        *reinterpret_cast<float4*>(&s_crd[t * 4]) = cp4[t];
    }
    int j  = t & 31;
    int rb = t >> 5;
    const float* fb = feat + (size_t)b * CC * NN + p0 + j;
    #pragma unroll
    for (int k = 0; k < 8; k++) {
        int row = rb + k * 8;
        sm[row][j] = __ldcs(&fb[(size_t)row * NN]);   // streamed once; keep L2 for staging
    }
    __syncthreads();                  // s_crd visible
    if (t < 32) {
        s_flat[t] = coord_to_flat(s_crd[t*3 + 0], s_crd[t*3 + 1], s_crd[t*3 + 2]);
    }

    // ---- wait for index_k's counts to be final ----
    cudaGridDependencySynchronize();

    if (t < 32) {
        int flat = s_flat[t];
        if (flat >= 0 && g_cnt[b*RV + flat] == 1)
            s_flat[t] = flat | 0x40000000;            // singleton marker
    }
    __syncthreads();

    int jp = t >> 3;                  // point in tile 0..31
    int q  = t & 7;                   // channel octet 0..7
    int tag = s_flat[jp];
    if (tag >= 0) {
        bool single = (tag & 0x40000000) != 0;
        int flat = tag & 0x3FFFFFFF;
        float* dst = g_stage + ((size_t)(b * RV + flat) * CC) + q * 8;
        int c0 = q * 8;
        float4 x = make_float4(sm[c0+0][jp], sm[c0+1][jp], sm[c0+2][jp], sm[c0+3][jp]);
        float4 y = make_float4(sm[c0+4][jp], sm[c0+5][jp], sm[c0+6][jp], sm[c0+7][jp]);
        if (single) {                 // sole writer of this row: plain stores (L2-resident)
            *reinterpret_cast<float4*>(dst)     = x;
            *reinterpret_cast<float4*>(dst + 4) = y;
        } else {                      // shared row: atomic reduction
            red_add_v4(dst,     x.x, x.y, x.z, x.w);
            red_add_v4(dst + 4, y.x, y.y, y.z, y.w);
        }
    }
}

// ---------------- finalize (PDL secondary): R13 load path, int4 count prologue -------
__global__ __launch_bounds__(256)
void finalize_k(float* __restrict__ out) {
    __shared__ float sm[64 * 65];     // [channel][voxel]
    __shared__ float s_inv[64];
    __shared__ int   s_cnt[64];
    int t = threadIdx.x;
    int gvbase = blockIdx.x * 64;

    cudaGridDependencySynchronize();  // everything below depends on scatter

    if (t < 16) {                     // int4: read own 4 counts, then clean own 4
        int4* cp = reinterpret_cast<int4*>(&g_cnt[gvbase + t * 4]);
        int4 c4 = *cp;
        s_cnt[t*4+0] = c4.x;  s_inv[t*4+0] = 1.f / (float)max(c4.x, 1);
        s_cnt[t*4+1] = c4.y;  s_inv[t*4+1] = 1.f / (float)max(c4.y, 1);
        s_cnt[t*4+2] = c4.z;  s_inv[t*4+2] = 1.f / (float)max(c4.z, 1);
        s_cnt[t*4+3] = c4.w;  s_inv[t*4+3] = 1.f / (float)max(c4.w, 1);
        *cp = make_int4(0, 0, 0, 0);  // self-clean, same-thread ordered
    }
    __syncthreads();

    float4* stg4 = reinterpret_cast<float4*>(g_stage + (size_t)gvbase * CC);  // 1024 float4
    #pragma unroll
    for (int k = 0; k < 4; k++) {
        int i   = t + 256 * k;        // float4 index within block
        int vox = i >> 4;
        int c4  = i & 15;
        float4 v = __ldcs(&stg4[i]);  // unconditional (MLP=4); dead after read
        float inv = s_inv[vox];
        int c0 = c4 * 4;
        sm[(c0+0) * 65 + vox] = v.x * inv;
        sm[(c0+1) * 65 + vox] = v.y * inv;
        sm[(c0+2) * 65 + vox] = v.z * inv;
        sm[(c0+3) * 65 + vox] = v.w * inv;
        if (s_cnt[vox] > 1) stg4[i] = make_float4(0.f, 0.f, 0.f, 0.f);  // clean RED rows
    }
    __syncthreads();

    int b  = blockIdx.x / GROUPS_PER_BATCH;
    int vb = (blockIdx.x % GROUPS_PER_BATCH) * 64;
    int c  = t >> 2;                  // 0..63
    int q  = t & 3;                   // 0..3 -> 16 voxels each
    float* ob = out + ((size_t)(b * CC + c)) * RV + vb + q * 16;
    const float* sp = &sm[c * 65 + q * 16];
    #pragma unroll
    for (int k = 0; k < 4; k++) {
        __stcs(reinterpret_cast<float4*>(ob + k*4),
               make_float4(sp[k*4+0], sp[k*4+1], sp[k*4+2], sp[k*4+3]));  // never re-read
    }
}

extern "C" void kernel_launch(void* const* d_in, const int* in_sizes, int n_in,
                              void* d_out, int out_size) {
    const float* feat   = (const float*)d_in[0];   // [B, C, N]
    const float* coords = (const float*)d_in[1];   // [B, N, 3]
    float* out = (float*)d_out;                    // [B, C, X, Y, Z]

    index_k<<<NPTS / 4 / 256, 256>>>(reinterpret_cast<const float4*>(coords)); // 256 blocks

    cudaLaunchAttribute pdl[1];
    pdl[0].id = cudaLaunchAttributeProgrammaticStreamSerialization;
    pdl[0].val.programmaticStreamSerializationAllowed = 1;

    {   // scatter: PDL secondary of index
        cudaLaunchConfig_t cfg = {};
        cfg.gridDim  = dim3(NN / 32, BB);
        cfg.blockDim = dim3(256);
        cfg.stream   = 0;
        cfg.attrs    = pdl;
        cfg.numAttrs = 1;
        cudaLaunchKernelEx(&cfg, scatter_k, feat, coords);
    }
    {   // finalize: PDL secondary of scatter
        cudaLaunchConfig_t cfg = {};
        cfg.gridDim  = dim3(FIN_BLOCKS);
        cfg.blockDim = dim3(256);
        cfg.stream   = 0;
        cfg.attrs    = pdl;
        cfg.numAttrs = 1;
        cudaLaunchKernelEx(&cfg, finalize_k, out);
    }
}